// round 15
// baseline (speedup 1.0000x reference)
#include <cuda_runtime.h>
#include <math_constants.h>

#define THREADS_MAIN 256    // 8 warps per block
#define BLOCKS_PER_SM 2
#define U 8                 // batch size (atoms per pipeline stage)
#define MAXW 4096           // max warps supported (grid capped accordingly)

// Head partial records + publish flags (fully rewritten every launch).
__device__ float4 g_sH[MAXW][32];   // head partial sums
__device__ float4 g_mH[MAXW][32];   // head partial maxs
__device__ int    g_cH[MAXW];       // head partial count
__device__ int    g_segH[MAXW];     // head segment id (-1 = none)
__device__ int    g_ptH[MAXW];      // head is pass-through (open both ends)
__device__ int    g_ready[MAXW];    // publish flag (0 -> 1 after threadfence)

__device__ __forceinline__ void f32x2_add(unsigned long long& acc, unsigned long long v) {
    asm("add.rn.f32x2 %0, %0, %1;" : "+l"(acc) : "l"(v));
}
__device__ __forceinline__ float2 unpack2(unsigned long long v) {
    float a, b;
    asm("mov.b64 {%0,%1}, %2;" : "=f"(a), "=f"(b) : "l"(v));
    return make_float2(a, b);
}
// Streaming (evict-first) accesses: these streams have zero reuse chip-wide.
__device__ __forceinline__ ulonglong2 ldcs16(const ulonglong2* p) {
    ulonglong2 r;
    asm("ld.global.cs.v2.u64 {%0,%1}, [%2];" : "=l"(r.x), "=l"(r.y) : "l"(p));
    return r;
}
__device__ __forceinline__ int4 ldcs_i4(const int* p) {
    int4 r;
    asm("ld.global.cs.v4.s32 {%0,%1,%2,%3}, [%4];"
        : "=r"(r.x), "=r"(r.y), "=r"(r.z), "=r"(r.w) : "l"(p));
    return r;
}
__device__ __forceinline__ void stcs16(float* p, float4 v) {
    asm volatile("st.global.cs.v4.f32 [%0], {%1,%2,%3,%4};"
                 :: "l"(p), "f"(v.x), "f"(v.y), "f"(v.z), "f"(v.w) : "memory");
}

// ---------------------------------------------------------------------------
// Single fused kernel, software-pipelined: while batch i is accumulated from
// one register buffer, batch i+1's 8 LDG.128 are in flight into the other.
// Warp-per-chunk segmented scan (lane l owns features [4l,4l+4)). Interior
// segments -> direct store with fused divide. Straddling segments: owner warp
// spins on later warps' published head partials (one resident wave -> safe).
// All zero-reuse streams (features, membership, output) use evict-first.
// ---------------------------------------------------------------------------
__global__ void __launch_bounds__(THREADS_MAIN, BLOCKS_PER_SM)
gg_main(const float* __restrict__ feat,
        const int*   __restrict__ mem,
        float*       __restrict__ out,
        int n_atoms, int chunk, int nwarps) {
    const int lane = threadIdx.x & 31;
    const int wg   = (blockIdx.x * blockDim.x + threadIdx.x) >> 5;

    if (lane == 0) g_ready[wg] = 0;     // reset long before any reader spins
    __syncwarp();

    long long astart = (long long)wg * chunk;
    if (astart >= n_atoms) {
        if (lane == 0) { g_segH[wg] = -1; __threadfence(); g_ready[wg] = 1; }
        return;
    }
    long long aend = astart + chunk;
    if (aend > n_atoms) aend = n_atoms;

    const ulonglong2* __restrict__ frow = (const ulonglong2*)feat;  // 32 per row

    int  seg = __ldg(mem + astart);
    bool began_inside = (astart == 0) || (__ldg(mem + astart - 1) != seg);

    unsigned long long s01 = 0, s23 = 0;   // packed f32x2 sums
    float4 m = make_float4(-CUDART_INF_F, -CUDART_INF_F, -CUDART_INF_F, -CUDART_INF_F);
    int cnt = 0;

    // Head partial buffered in registers until the end.
    int    hseg = -1, hpt = 0, hcnt = 0;
    float4 hsum = make_float4(0.f, 0.f, 0.f, 0.f);
    float4 hmax = hsum;

    auto store_full = [&](int sg) {
        float2 a2 = unpack2(s01), b2 = unpack2(s23);
        float r = 1.0f / (float)cnt;
        float* om = out + (size_t)sg * 256 + lane * 4;
        stcs16(om,       make_float4(a2.x * r, a2.y * r, b2.x * r, b2.y * r));
        stcs16(om + 128, m);
    };
    auto buffer_head = [&](int sg, int pt) {
        float2 a2 = unpack2(s01), b2 = unpack2(s23);
        hsum = make_float4(a2.x, a2.y, b2.x, b2.y);
        hmax = m; hcnt = cnt; hseg = sg; hpt = pt;
    };
    auto flush_mid = [&](int sg) {       // segment ended inside the chunk
        if (began_inside) store_full(sg);
        else              buffer_head(sg, 0);
        began_inside = true;
    };
    auto reset = [&]() {
        s01 = 0; s23 = 0;
        m = make_float4(-CUDART_INF_F, -CUDART_INF_F, -CUDART_INF_F, -CUDART_INF_F);
        cnt = 0;
    };
    auto accum = [&](ulonglong2 v) {
        f32x2_add(s01, v.x);
        f32x2_add(s23, v.y);
        float2 a2 = unpack2(v.x), b2 = unpack2(v.y);
        m.x = fmaxf(m.x, a2.x); m.y = fmaxf(m.y, a2.y);
        m.z = fmaxf(m.z, b2.x); m.w = fmaxf(m.w, b2.y);
    };

    // ---- software-pipelined bulk loop ----
    ulonglong2 vA[U], vB[U];
    int4 mA0, mA1, mB0, mB1;

    long long a = astart;
    long long nfull = (aend - a) / U;

#define LOADB(VV, M0, M1, BASE)                                   \
    do {                                                           \
        M0 = ldcs_i4(mem + (BASE));                                \
        M1 = ldcs_i4(mem + (BASE) + 4);                            \
        _Pragma("unroll")                                          \
        for (int u = 0; u < U; ++u)                                \
            VV[u] = ldcs16(&frow[((BASE) + u) * 32 + lane]);       \
    } while (0)

#define ACCB(VV, M0, M1)                                           \
    do {                                                           \
        if (M0.x == M1.w) {                                        \
            if (M0.x != seg) { flush_mid(seg); seg = M0.x; reset(); } \
            _Pragma("unroll")                                      \
            for (int u = 0; u < U; ++u) accum(VV[u]);              \
            cnt += U;                                              \
        } else {                                                   \
            int mbs[U] = {M0.x, M0.y, M0.z, M0.w,                  \
                          M1.x, M1.y, M1.z, M1.w};                 \
            _Pragma("unroll")                                      \
            for (int u = 0; u < U; ++u) {                          \
                if (mbs[u] != seg) { flush_mid(seg); seg = mbs[u]; reset(); } \
                accum(VV[u]);                                      \
                ++cnt;                                             \
            }                                                      \
        }                                                          \
    } while (0)

    if (nfull > 0) LOADB(vA, mA0, mA1, a);
    long long i = 0;
    for (; i + 2 <= nfull; i += 2) {
        LOADB(vB, mB0, mB1, a + U);          // prefetch batch i+1
        ACCB(vA, mA0, mA1);  a += U;         // consume batch i
        if (i + 2 < nfull) LOADB(vA, mA0, mA1, a + U);   // prefetch batch i+2
        ACCB(vB, mB0, mB1);  a += U;         // consume batch i+1
    }
    if (i < nfull) {                          // odd remainder: already in vA
        ACCB(vA, mA0, mA1);  a += U;
    }
#undef LOADB
#undef ACCB

    // ---- scalar tail (last active warp only) ----
    for (; a < aend; ++a) {
        int mb = __ldg(mem + a);
        ulonglong2 v = ldcs16(&frow[a * 32 + lane]);
        if (mb != seg) { flush_mid(seg); seg = mb; reset(); }
        accum(v);
        ++cnt;
    }

    bool ended_inside = (aend == n_atoms) || (__ldg(mem + aend) != seg);
    int tseg = -1;
    if (ended_inside) {
        if (began_inside) store_full(seg);
        else              buffer_head(seg, 0);
    } else {
        if (began_inside) tseg = seg;            // this warp owns the straddler
        else              buffer_head(seg, 1);   // pass-through chunk
    }

    // ---- publish head record, then ready flag (release) ----
    if (hseg >= 0) {
        g_sH[wg][lane] = hsum;
        g_mH[wg][lane] = hmax;
        if (lane == 0) { g_cH[wg] = hcnt; g_ptH[wg] = hpt; }
    }
    if (lane == 0) g_segH[wg] = hseg;
    __threadfence();
    if (lane == 0) ((volatile int*)g_ready)[wg] = 1;

    // ---- owner combines its straddling segment in-kernel ----
    if (tseg >= 0) {
        float2 x = unpack2(s01), y = unpack2(s23);
        float4 S = make_float4(x.x, x.y, y.x, y.y);
        float4 M = m;
        int    C = cnt;
        for (int j = wg + 1; j < nwarps; ++j) {
            if (lane == 0) {
                while (((volatile int*)g_ready)[j] == 0) __nanosleep(64);
            }
            __syncwarp();
            __threadfence();                      // acquire
            if (__ldcg(&g_segH[j]) != tseg) break;
            float4 hs = __ldcg(&g_sH[j][lane]);
            float4 hm = __ldcg(&g_mH[j][lane]);
            S.x += hs.x; S.y += hs.y; S.z += hs.z; S.w += hs.w;
            M.x = fmaxf(M.x, hm.x); M.y = fmaxf(M.y, hm.y);
            M.z = fmaxf(M.z, hm.z); M.w = fmaxf(M.w, hm.w);
            C += __ldcg(&g_cH[j]);
            if (!__ldcg(&g_ptH[j])) break;        // segment ended inside warp j
        }
        float r = 1.0f / (float)C;
        float* om = out + (size_t)tseg * 256 + lane * 4;
        stcs16(om,       make_float4(S.x * r, S.y * r, S.z * r, S.w * r));
        stcs16(om + 128, M);
    }
}

// ---------------------------------------------------------------------------
extern "C" void kernel_launch(void* const* d_in, const int* in_sizes, int n_in,
                              void* d_out, int out_size) {
    const float* feat = (const float*)d_in[0];
    const int*   mem  = (const int*)d_in[1];
    float*       out  = (float*)d_out;

    int n_atoms = in_sizes[1];          // membership element count

    // Exactly one resident wave: SM_count * BLOCKS_PER_SM blocks, 8 warps each.
    int sm_count = 152;
    cudaDeviceGetAttribute(&sm_count, cudaDevAttrMultiProcessorCount, 0);
    int nblocks = sm_count * BLOCKS_PER_SM;
    int max_blocks = MAXW / (THREADS_MAIN / 32);
    if (nblocks > max_blocks) nblocks = max_blocks;
    int nwarps = nblocks * (THREADS_MAIN / 32);
    long long chunk_ll = ((long long)n_atoms + nwarps - 1) / nwarps;
    int chunk = (int)((chunk_ll + U - 1) / U) * U;   // multiple of 8 (int4 alignment)

    gg_main<<<nblocks, THREADS_MAIN>>>(feat, mem, out, n_atoms, chunk, nwarps);
}

// round 16
// speedup vs baseline: 1.0343x; 1.0343x over previous
#include <cuda_runtime.h>
#include <math_constants.h>

#define THREADS_MAIN 256    // 8 warps per block
#define BLOCKS_PER_SM 2
#define U 8                 // batch size (atoms per pipeline stage)
#define MAXW 4096           // max warps supported (grid capped accordingly)

// Head partial records + publish flags (fully rewritten every launch).
__device__ float4 g_sH[MAXW][32];   // head partial sums
__device__ float4 g_mH[MAXW][32];   // head partial maxs
__device__ int    g_cH[MAXW];       // head partial count
__device__ int    g_segH[MAXW];     // head segment id (-1 = none)
__device__ int    g_ptH[MAXW];      // head is pass-through (open both ends)
__device__ int    g_ready[MAXW];    // publish flag (0 -> 1 after threadfence)

__device__ __forceinline__ void f32x2_add(unsigned long long& acc, unsigned long long v) {
    asm("add.rn.f32x2 %0, %0, %1;" : "+l"(acc) : "l"(v));
}
__device__ __forceinline__ float2 unpack2(unsigned long long v) {
    float a, b;
    asm("mov.b64 {%0,%1}, %2;" : "=f"(a), "=f"(b) : "l"(v));
    return make_float2(a, b);
}
// Streaming (evict-first) 16B load: features are read exactly once chip-wide.
__device__ __forceinline__ ulonglong2 ldcs16(const ulonglong2* p) {
    ulonglong2 r;
    asm("ld.global.cs.v2.u64 {%0,%1}, [%2];" : "=l"(r.x), "=l"(r.y) : "l"(p));
    return r;
}
// Streaming store: output written once, never re-read in-kernel.
__device__ __forceinline__ void stcs16(float* p, float4 v) {
    asm volatile("st.global.cs.v4.f32 [%0], {%1,%2,%3,%4};"
                 :: "l"(p), "f"(v.x), "f"(v.y), "f"(v.z), "f"(v.w) : "memory");
}

// ---------------------------------------------------------------------------
// Single fused kernel, software-pipelined: while batch i is accumulated from
// one register buffer, batch i+1's 8 LDG.128 are in flight into the other.
// Warp-per-chunk segmented scan (lane l owns features [4l,4l+4)). Interior
// segments -> direct store with fused divide. Straddling segments: owner warp
// spins on later warps' published head partials (one resident wave -> safe).
// Features: ld.cs (zero reuse). Membership: default (L1 reuse across batches).
// Output: st.cs (written once).
// ---------------------------------------------------------------------------
__global__ void __launch_bounds__(THREADS_MAIN, BLOCKS_PER_SM)
gg_main(const float* __restrict__ feat,
        const int*   __restrict__ mem,
        float*       __restrict__ out,
        int n_atoms, int chunk, int nwarps) {
    const int lane = threadIdx.x & 31;
    const int wg   = (blockIdx.x * blockDim.x + threadIdx.x) >> 5;

    if (lane == 0) g_ready[wg] = 0;     // reset long before any reader spins
    __syncwarp();

    long long astart = (long long)wg * chunk;
    if (astart >= n_atoms) {
        if (lane == 0) { g_segH[wg] = -1; __threadfence(); g_ready[wg] = 1; }
        return;
    }
    long long aend = astart + chunk;
    if (aend > n_atoms) aend = n_atoms;

    const ulonglong2* __restrict__ frow = (const ulonglong2*)feat;  // 32 per row

    int  seg = __ldg(mem + astart);
    bool began_inside = (astart == 0) || (__ldg(mem + astart - 1) != seg);

    unsigned long long s01 = 0, s23 = 0;   // packed f32x2 sums
    float4 m = make_float4(-CUDART_INF_F, -CUDART_INF_F, -CUDART_INF_F, -CUDART_INF_F);
    int cnt = 0;

    // Head partial buffered in registers until the end.
    int    hseg = -1, hpt = 0, hcnt = 0;
    float4 hsum = make_float4(0.f, 0.f, 0.f, 0.f);
    float4 hmax = hsum;

    auto store_full = [&](int sg) {
        float2 a2 = unpack2(s01), b2 = unpack2(s23);
        float r = 1.0f / (float)cnt;
        float* om = out + (size_t)sg * 256 + lane * 4;
        stcs16(om,       make_float4(a2.x * r, a2.y * r, b2.x * r, b2.y * r));
        stcs16(om + 128, m);
    };
    auto buffer_head = [&](int sg, int pt) {
        float2 a2 = unpack2(s01), b2 = unpack2(s23);
        hsum = make_float4(a2.x, a2.y, b2.x, b2.y);
        hmax = m; hcnt = cnt; hseg = sg; hpt = pt;
    };
    auto flush_mid = [&](int sg) {       // segment ended inside the chunk
        if (began_inside) store_full(sg);
        else              buffer_head(sg, 0);
        began_inside = true;
    };
    auto reset = [&]() {
        s01 = 0; s23 = 0;
        m = make_float4(-CUDART_INF_F, -CUDART_INF_F, -CUDART_INF_F, -CUDART_INF_F);
        cnt = 0;
    };
    auto accum = [&](ulonglong2 v) {
        f32x2_add(s01, v.x);
        f32x2_add(s23, v.y);
        float2 a2 = unpack2(v.x), b2 = unpack2(v.y);
        m.x = fmaxf(m.x, a2.x); m.y = fmaxf(m.y, a2.y);
        m.z = fmaxf(m.z, b2.x); m.w = fmaxf(m.w, b2.y);
    };

    // ---- software-pipelined bulk loop ----
    ulonglong2 vA[U], vB[U];
    int4 mA0, mA1, mB0, mB1;

    long long a = astart;
    long long nfull = (aend - a) / U;

#define LOADB(VV, M0, M1, BASE)                                   \
    do {                                                           \
        M0 = *(const int4*)(mem + (BASE));                         \
        M1 = *(const int4*)(mem + (BASE) + 4);                     \
        _Pragma("unroll")                                          \
        for (int u = 0; u < U; ++u)                                \
            VV[u] = ldcs16(&frow[((BASE) + u) * 32 + lane]);       \
    } while (0)

#define ACCB(VV, M0, M1)                                           \
    do {                                                           \
        if (M0.x == M1.w) {                                        \
            if (M0.x != seg) { flush_mid(seg); seg = M0.x; reset(); } \
            _Pragma("unroll")                                      \
            for (int u = 0; u < U; ++u) accum(VV[u]);              \
            cnt += U;                                              \
        } else {                                                   \
            int mbs[U] = {M0.x, M0.y, M0.z, M0.w,                  \
                          M1.x, M1.y, M1.z, M1.w};                 \
            _Pragma("unroll")                                      \
            for (int u = 0; u < U; ++u) {                          \
                if (mbs[u] != seg) { flush_mid(seg); seg = mbs[u]; reset(); } \
                accum(VV[u]);                                      \
                ++cnt;                                             \
            }                                                      \
        }                                                          \
    } while (0)

    if (nfull > 0) LOADB(vA, mA0, mA1, a);
    long long i = 0;
    for (; i + 2 <= nfull; i += 2) {
        LOADB(vB, mB0, mB1, a + U);          // prefetch batch i+1
        ACCB(vA, mA0, mA1);  a += U;         // consume batch i
        if (i + 2 < nfull) LOADB(vA, mA0, mA1, a + U);   // prefetch batch i+2
        ACCB(vB, mB0, mB1);  a += U;         // consume batch i+1
    }
    if (i < nfull) {                          // odd remainder: already in vA
        ACCB(vA, mA0, mA1);  a += U;
    }
#undef LOADB
#undef ACCB

    // ---- scalar tail (last active warp only) ----
    for (; a < aend; ++a) {
        int mb = __ldg(mem + a);
        ulonglong2 v = ldcs16(&frow[a * 32 + lane]);
        if (mb != seg) { flush_mid(seg); seg = mb; reset(); }
        accum(v);
        ++cnt;
    }

    bool ended_inside = (aend == n_atoms) || (__ldg(mem + aend) != seg);
    int tseg = -1;
    if (ended_inside) {
        if (began_inside) store_full(seg);
        else              buffer_head(seg, 0);
    } else {
        if (began_inside) tseg = seg;            // this warp owns the straddler
        else              buffer_head(seg, 1);   // pass-through chunk
    }

    // ---- publish head record, then ready flag (release) ----
    if (hseg >= 0) {
        g_sH[wg][lane] = hsum;
        g_mH[wg][lane] = hmax;
        if (lane == 0) { g_cH[wg] = hcnt; g_ptH[wg] = hpt; }
    }
    if (lane == 0) g_segH[wg] = hseg;
    __threadfence();
    if (lane == 0) ((volatile int*)g_ready)[wg] = 1;

    // ---- owner combines its straddling segment in-kernel ----
    if (tseg >= 0) {
        float2 x = unpack2(s01), y = unpack2(s23);
        float4 S = make_float4(x.x, x.y, y.x, y.y);
        float4 M = m;
        int    C = cnt;
        for (int j = wg + 1; j < nwarps; ++j) {
            if (lane == 0) {
                while (((volatile int*)g_ready)[j] == 0) __nanosleep(64);
            }
            __syncwarp();
            __threadfence();                      // acquire
            if (__ldcg(&g_segH[j]) != tseg) break;
            float4 hs = __ldcg(&g_sH[j][lane]);
            float4 hm = __ldcg(&g_mH[j][lane]);
            S.x += hs.x; S.y += hs.y; S.z += hs.z; S.w += hs.w;
            M.x = fmaxf(M.x, hm.x); M.y = fmaxf(M.y, hm.y);
            M.z = fmaxf(M.z, hm.z); M.w = fmaxf(M.w, hm.w);
            C += __ldcg(&g_cH[j]);
            if (!__ldcg(&g_ptH[j])) break;        // segment ended inside warp j
        }
        float r = 1.0f / (float)C;
        float* om = out + (size_t)tseg * 256 + lane * 4;
        stcs16(om,       make_float4(S.x * r, S.y * r, S.z * r, S.w * r));
        stcs16(om + 128, M);
    }
}

// ---------------------------------------------------------------------------
extern "C" void kernel_launch(void* const* d_in, const int* in_sizes, int n_in,
                              void* d_out, int out_size) {
    const float* feat = (const float*)d_in[0];
    const int*   mem  = (const int*)d_in[1];
    float*       out  = (float*)d_out;

    int n_atoms = in_sizes[1];          // membership element count

    // Exactly one resident wave: SM_count * BLOCKS_PER_SM blocks, 8 warps each.
    int sm_count = 152;
    cudaDeviceGetAttribute(&sm_count, cudaDevAttrMultiProcessorCount, 0);
    int nblocks = sm_count * BLOCKS_PER_SM;
    int max_blocks = MAXW / (THREADS_MAIN / 32);
    if (nblocks > max_blocks) nblocks = max_blocks;
    int nwarps = nblocks * (THREADS_MAIN / 32);
    long long chunk_ll = ((long long)n_atoms + nwarps - 1) / nwarps;
    int chunk = (int)((chunk_ll + U - 1) / U) * U;   // multiple of 8 (int4 alignment)

    gg_main<<<nblocks, THREADS_MAIN>>>(feat, mem, out, n_atoms, chunk, nwarps);
}